// round 11
// baseline (speedup 1.0000x reference)
#include <cuda_runtime.h>

// Fused bleed-correction, v4.1: f materialized at load, no src tile in smem.
// (Resubmission of v4 after infra failure; kernel-coeff loads hoisted for overlap.)
//
// out[i] = src[i] - sum_{j in {i-1,i+1}} [ conv3x3(src[j], kA) + conv3x3(f_ij, kB) ]
//   with f_ij = (src[j]^0.5 * src[i])^(2/3) = cbrt(src[j] * src[i]^2)
// conv = cross-correlation, SAME zero pad.
//
// Tile: one block = 512 (full width) x 8 rows of one (channel, image).
// Full-width tiles -> x halo is always the image border (zero) -> no x predication.
//
// f is computed ONCE PER PIXEL during the neighbor-tile load (while the LDG
// value is still in registers), not 2.25x redundantly inside the conv sweep.
// smem holds {n, f} (src is never stored); the sweep is a pure dual-conv:
// 24 LDS + 288 FFMA per thread per neighbor, no MUFU, no feeders.
// The epilogue re-reads the src center from global (L2 hit).
//
// smem layout is offset-by-1 (logical col c at phys c+1) so conv reads are one
// aligned LDS.128 + LDS.64 per row; the +1 shift during stores is done via
// __shfl_up of the lane-boundary element (n and f shifted identically).

namespace {

constexpr int Ww   = 512;
constexpr int TH   = 8;
constexpr int SROWS = TH + 2;      // 10 rows (y halo)
constexpr int SW_   = 516;         // row stride: data phys [0..512], zero pad at 513
constexpr int NTHREADS = 256;

__device__ __forceinline__ float cbrt_nonneg(float x) {
    // x >= 0. lg2(0) = -inf -> ex2 -> 0, matches zero padding.
    return __powf(x, 0.3333333333333333f);
}

__global__ __launch_bounds__(NTHREADS, 4)
void bleed_kernel(const float* __restrict__ sources,
                  const float* __restrict__ kernels,
                  float* __restrict__ out)
{
    __shared__ __align__(16) float s_n[SROWS * SW_];   // raw neighbor tile
    __shared__ __align__(16) float s_f[SROWS * SW_];   // f = cbrt(nb * src^2)

    // Channel innermost -> adjacent-channel blocks of the same (img, y-tile)
    // run in the same wave -> L2 reuse of shared source tiles.
    const int bid = blockIdx.x;
    const int ch  = bid & 3;
    const int img = (bid >> 2) & 31;
    const int gy0 = (bid >> 7) * TH;    // 64 y-tiles

    const int tid  = threadIdx.x;
    const int lane = tid & 31;
    const int c4   = tid & 127;         // float4 column index (0..127)
    const int lx   = c4 * 4;
    const int r0   = tid >> 7;          // 0 or 1
    const int oyb  = r0 * 4;            // output row base within tile

    const size_t imgStride = (size_t)Ww * Ww;
    const float* srcBase = sources + ((size_t)ch * 32 + img) * imgStride;

    // zero the phys-col-513 pad (read by the sweep's far-halo LDS.64)
    if (tid < SROWS) {
        s_n[tid * SW_ + 513] = 0.f;
        s_f[tid * SW_ + 513] = 0.f;
    }

    float acc[4][4];
    #pragma unroll
    for (int o = 0; o < 4; o++)
        #pragma unroll
        for (int c = 0; c < 4; c++) acc[o][c] = 0.f;

    // Neighbor + kernel-index table (reference kidx order: off=-1 then off=+1)
    int nnb, nbj0, nbj1, kc0, kc1;
    switch (ch) {
        case 0:  nnb = 1; nbj0 = 1; kc0 = 0;  nbj1 = 0; kc1 = 0;  break;
        case 1:  nnb = 2; nbj0 = 0; kc0 = 2;  nbj1 = 2; kc1 = 4;  break;
        case 2:  nnb = 2; nbj0 = 1; kc0 = 6;  nbj1 = 3; kc1 = 8;  break;
        default: nnb = 1; nbj0 = 2; kc0 = 10; nbj1 = 0; kc1 = 0;  break;
    }

    for (int s = 0; s < nnb; s++) {
        const int j  = (s == 0) ? nbj0 : nbj1;
        const int kc = (s == 0) ? kc0  : kc1;
        const float* nbBase = sources + ((size_t)j * 32 + img) * imgStride;

        // conv kernels for this neighbor — issued first so their LDG latency
        // overlaps the tile-load pass below (uniform, L2-resident).
        float kA[9], kB[9];
        #pragma unroll
        for (int t = 0; t < 9; t++) {
            kA[t] = __ldg(kernels + kc * 9 + t);
            kB[t] = __ldg(kernels + (kc + 1) * 9 + t);
        }

        // ---- fused load + f materialization (one pass, f computed ONCE/pixel) ----
        #pragma unroll
        for (int r = r0; r < SROWS; r += 2) {
            const int gy = gy0 + r - 1;
            const bool inr = (unsigned)gy < (unsigned)Ww;
            float4 vn = make_float4(0.f, 0.f, 0.f, 0.f);
            float4 vs = make_float4(0.f, 0.f, 0.f, 0.f);
            if (inr) {
                const float* nrow = nbBase  + (size_t)gy * Ww;
                const float* srow = srcBase + (size_t)gy * Ww;
                vn = __ldg((const float4*)nrow + c4);
                vs = __ldg((const float4*)srow + c4);
            }
            float4 vf;
            vf.x = cbrt_nonneg(vn.x * vs.x * vs.x);
            vf.y = cbrt_nonneg(vn.y * vs.y * vs.y);
            vf.z = cbrt_nonneg(vn.z * vs.z * vs.z);
            vf.w = cbrt_nonneg(vn.w * vs.w * vs.w);

            // shift right by one: phys slot lx gets logical col lx-1
            float un = __shfl_up_sync(0xffffffffu, vn.w, 1);
            float uf = __shfl_up_sync(0xffffffffu, vf.w, 1);
            if (lane == 0) {
                un = 0.f; uf = 0.f;                 // c4==0: logical -1 = 0
                if (c4 != 0 && inr) {
                    un = __ldg(nbBase  + (size_t)gy * Ww + lx - 1);
                    float us = __ldg(srcBase + (size_t)gy * Ww + lx - 1);
                    uf = cbrt_nonneg(un * us * us);
                }
            }
            float* rn = s_n + r * SW_;
            float* rf = s_f + r * SW_;
            *(float4*)(rn + lx) = make_float4(un, vn.x, vn.y, vn.z);
            *(float4*)(rf + lx) = make_float4(uf, vf.x, vf.y, vf.z);
            if (c4 == 127) {                        // logical col 511 -> phys 512
                rn[512] = vn.w;
                rf[512] = vf.w;
            }
        }

        __syncthreads();    // {n, f} tiles visible

        // ---- pure dual-conv sweep: acc += kA (x) n + kB (x) f ----
        #pragma unroll
        for (int iy = 0; iy < 6; iy++) {
            const float* rn = s_n + (oyb + iy) * SW_ + lx;  // 16B aligned
            const float* rf = s_f + (oyb + iy) * SW_ + lx;
            float4 n0 = *(const float4*)rn;
            float2 n1 = *(const float2*)(rn + 4);
            float4 f0 = *(const float4*)rf;
            float2 f1 = *(const float2*)(rf + 4);
            float n[6] = {n0.x, n0.y, n0.z, n0.w, n1.x, n1.y};
            float f[6] = {f0.x, f0.y, f0.z, f0.w, f1.x, f1.y};

            #pragma unroll
            for (int o = 0; o < 4; o++) {
                const int kr = iy - o;              // kernel row index
                if (kr >= 0 && kr < 3) {
                    #pragma unroll
                    for (int c = 0; c < 4; c++) {
                        float a = acc[o][c];
                        a = fmaf(kA[kr * 3 + 0], n[c + 0], a);
                        a = fmaf(kA[kr * 3 + 1], n[c + 1], a);
                        a = fmaf(kA[kr * 3 + 2], n[c + 2], a);
                        a = fmaf(kB[kr * 3 + 0], f[c + 0], a);
                        a = fmaf(kB[kr * 3 + 1], f[c + 1], a);
                        a = fmaf(kB[kr * 3 + 2], f[c + 2], a);
                        acc[o][c] = a;
                    }
                }
            }
        }

        if (s + 1 < nnb) __syncthreads();   // before next neighbor overwrites tiles
    }

    // ---- epilogue: out = src - bleed; src center re-read from global (L2 hit) ----
    float* outBase = out + ((size_t)ch * 32 + img) * imgStride;
    #pragma unroll
    for (int o = 0; o < 4; o++) {
        const int gy = gy0 + oyb + o;
        float4 sv = __ldg((const float4*)(srcBase + (size_t)gy * Ww) + c4);
        float4 r;
        r.x = sv.x - acc[o][0];
        r.y = sv.y - acc[o][1];
        r.z = sv.z - acc[o][2];
        r.w = sv.w - acc[o][3];
        *(float4*)(outBase + (size_t)gy * Ww + lx) = r;
    }
}

}  // namespace

extern "C" void kernel_launch(void* const* d_in, const int* in_sizes, int n_in,
                              void* d_out, int out_size) {
    (void)in_sizes; (void)n_in; (void)out_size;
    const float* sources = (const float*)d_in[0];   // (4,32,512,512,1) fp32
    const float* kernels = (const float*)d_in[1];   // (12,3,3) fp32
    float* out = (float*)d_out;                     // (4,32,512,512,1) fp32

    // 4 channels * 32 images * 64 y-tiles = 8192 blocks
    bleed_kernel<<<8192, NTHREADS>>>(sources, kernels, out);
}